// round 16
// baseline (speedup 1.0000x reference)
#include <cuda_runtime.h>

#define GRID_N 32
#define CELLS  1024
#define RS     33              // smem row stride (33 ≡ 1 mod 32: conflict-free)
#define NT     1024            // warp per row
#define ESW    4
#define WARMUP 28              // ≥ #row-crossings; unchecked sweeps
#define FM     0xffffffffu

__global__ void __launch_bounds__(NT, 1)
dijkstra_grid_kernel(const float* __restrict__ wg, float* __restrict__ out)
{
    __shared__ float ds[GRID_N * RS];
    __shared__ unsigned short pred[CELLS], pred2[CELLS], pred3[CELLS], pred4[CELLS];
    __shared__ unsigned char  mark[CELLS];

    volatile float* vs = ds;

    const int b = blockIdx.x;
    const int t = threadIdx.x;
    const int x = t & 31;               // lane = column
    const int y = t >> 5;               // warp = row
    const float INF = __int_as_float(0x7f800000);

    const float w = wg[(size_t)b * CELLS + t];   // cost to ENTER my cell

    // inclusive prefix (left) / suffix (right) weight sums within the row
    float pre = w, suf = w;
#pragma unroll
    for (int k = 1; k < 32; k <<= 1) {
        float s = __shfl_up_sync(FM, pre, k);   if (x >= k)      pre += s;
        float z = __shfl_down_sync(FM, suf, k); if (x < 32 - k)  suf += z;
    }

    float d = (t == 0) ? 0.0f : INF;
    ds[y * RS + x] = d;
    mark[t] = 0;
    __syncthreads();

    // One sweep:
    //  (1) vertical + diagonal relax from rows y±1 (smem Jacobi, chaotic),
    //  (2) FULL lateral closure left->right and right->left via exclusive
    //      warp min-scans over key = d - prefix(w):
    //      candidate from y' on the same row = (d[y']-pre[y']) + pre[x]
    //      == d[y'] + sum of entered-cell weights (up to float reordering).
    // All values are monotone-decreasing upper bounds of true path costs
    // (within ~1e-6 reordering error); fminf-only updates converge to the
    // min-plus fixed point of this operator.
#define SWEEP()                                                                 \
    do {                                                                        \
        float up = (y > 0)  ? vs[(y - 1) * RS + x] : INF;                       \
        float dn = (y < 31) ? vs[(y + 1) * RS + x] : INF;                       \
        float ul = __shfl_up_sync(FM, up, 1),  ur = __shfl_down_sync(FM, up, 1);\
        float dl = __shfl_up_sync(FM, dn, 1),  dr = __shfl_down_sync(FM, dn, 1);\
        /* edge lanes receive their own up/dn: duplicate of a vertical term */  \
        float vmin = fminf(fminf(up, dn),                                       \
                           fminf(fminf(ul, ur), fminf(dl, dr)));                \
        d = fminf(d, vmin + w);                                                 \
        /* left-to-right closure: exclusive min-scan of (d - pre) */            \
        float eL = __shfl_up_sync(FM, d - pre, 1);                              \
        if (x == 0) eL = INF;                                                   \
        _Pragma("unroll")                                                       \
        for (int k = 1; k < 32; k <<= 1) {                                      \
            float s = __shfl_up_sync(FM, eL, k);                                \
            if (x >= k) eL = fminf(eL, s);                                      \
        }                                                                       \
        d = fminf(d, eL + pre);                                                 \
        /* right-to-left closure: exclusive min-scan of (d - suf) */            \
        float eR = __shfl_down_sync(FM, d - suf, 1);                            \
        if (x == 31) eR = INF;                                                  \
        _Pragma("unroll")                                                       \
        for (int k = 1; k < 32; k <<= 1) {                                      \
            float s = __shfl_down_sync(FM, eR, k);                              \
            if (x < 32 - k) eR = fminf(eR, s);                                  \
        }                                                                       \
        d = fminf(d, eR + suf);                                                 \
        vs[y * RS + x] = d;                                                     \
    } while (0)

    // warm-up: barriers serve only termination detection; paths need ~31
    // row-crossings, so the first WARMUP sweeps run with zero sync overhead.
    for (int k = 0; k < WARMUP; k++) SWEEP();

    // checked epochs: HW barrier-reduction termination
    for (;;) {
        const float sd = d;
#pragma unroll
        for (int k = 0; k < ESW; k++) SWEEP();
        // d monotone-decreasing: an epoch with no change anywhere => fixed point
        if (!__syncthreads_or(d != sd)) break;
    }
#undef SWEEP

    // ---- predecessor = argmin over 8 neighbor distances (unique a.s.) ----
    {
        float bd = INF; int bi = 0;
        const int dy8[8] = {-1, -1, -1, 0, 0, 1, 1, 1};
        const int dx8[8] = {-1,  0,  1,-1, 1,-1, 0, 1};
#pragma unroll
        for (int k = 0; k < 8; k++) {
            const int yy = y + dy8[k], xx = x + dx8[k];
            float v = (yy >= 0 && yy < 32 && xx >= 0 && xx < 32)
                      ? ds[yy * RS + xx] : INF;
            if (v < bd) { bd = v; bi = yy * GRID_N + xx; }
        }
        pred[t] = (unsigned short)bi;
    }
    __syncthreads();

    // ---- skip pointers: pred2 = pred∘pred; pred3/pred4 ----
    pred2[t] = pred[pred[t]];
    __syncthreads();
    {
        const int q = pred2[t];
        pred3[t] = pred[q];
        pred4[t] = pred2[q];
    }
    __syncthreads();

    // ---- backtrack from (31,31), 4 chain cells per iteration ----
    // dist strictly decreases along pred, so the chain reaches cell 0.
    if (t == 0) {
        int cur = CELLS - 1;
        for (int i = 0; i < CELLS / 4 + 2; i++) {
            const int m1 = pred[cur];
            const int m2 = pred2[cur];
            const int m3 = pred3[cur];
            const int nx = pred4[cur];
            mark[cur] = 1;
            if (cur == 0) break;
            mark[m1] = 1;
            if (m1 == 0) break;
            mark[m2] = 1;
            if (m2 == 0) break;
            mark[m3] = 1;
            if (m3 == 0) break;
            cur = nx;
        }
    }
    __syncthreads();

    // ---- coalesced output ----
    out[(size_t)b * CELLS + t] = mark[t] ? 1.0f : 0.0f;
}

extern "C" void kernel_launch(void* const* d_in, const int* in_sizes, int n_in,
                              void* d_out, int out_size)
{
    const float* w = (const float*)d_in[0];
    float* out = (float*)d_out;
    int batches = in_sizes[0] / CELLS;     // 128
    dijkstra_grid_kernel<<<batches, NT>>>(w, out);
}

// round 17
// speedup vs baseline: 2.3381x; 2.3381x over previous
#include <cuda_runtime.h>

#define GRID_N 32
#define CELLS  1024
#define SROW   24              // smem row stride: 2*SROW % 32 == 16 -> conflict-free
#define NROWS  34
#define NT     256
#define ESW    2               // sweeps per termination check (tight tail)
#define WARMUP 16              // unchecked sweeps (>=16 block-hops required)

__global__ void __launch_bounds__(NT, 1)
dijkstra_grid_kernel(const float* __restrict__ wg, float* __restrict__ out)
{
    __shared__ float Ea[NROWS * SROW];      // even-x columns
    __shared__ float Oa[NROWS * SROW];      // odd-x columns
    __shared__ unsigned short pred[CELLS];
    __shared__ unsigned short pred2[CELLS];
    __shared__ unsigned short pred3[CELLS];
    __shared__ unsigned short pred4[CELLS];
    __shared__ unsigned char  mark[CELLS];

    volatile float* E = Ea;
    volatile float* O = Oa;

    const int b  = blockIdx.x;
    const int t  = threadIdx.x;
    const int tx = t & 15;
    const int ty = t >> 4;
    const float INF = __int_as_float(0x7f800000);

    const int x0 = tx * 2, y0 = ty * 2;
    const int rt = y0, ra = y0 + 1, rc = y0 + 2, rb = y0 + 3;

    const float2* w2 = (const float2*)(wg + (size_t)b * CELLS);
    const float2 wAB = w2[y0 * 16 + tx];
    const float2 wCD = w2[(y0 + 1) * 16 + tx];
    const float wa = wAB.x, wb = wAB.y, wc = wCD.x, wd = wCD.y;

    for (int i = t; i < NROWS * SROW; i += NT) { Ea[i] = INF; Oa[i] = INF; }
    for (int i = t; i < CELLS; i += NT) mark[i] = 0;
    __syncthreads();

    float a = (t == 0) ? 0.0f : INF;        // (y0,   x0)
    float bv = INF;                          // (y0,   x0+1)
    float c = INF;                           // (y0+1, x0)
    float d = INF;                           // (y0+1, x0+1)
    Ea[ra * SROW + tx] = a;  Oa[ra * SROW + tx + 1] = bv;
    Ea[rc * SROW + tx] = c;  Oa[rc * SROW + tx + 1] = d;
    __syncthreads();

    // Proven R7/R10 sweep: front-batched halo loads + bidirectional 2x2
    // register Gauss-Seidel + write-through. Every candidate is d[nb] + w
    // (RN): exact, monotone-decreasing, reference-attainable path sums;
    // unique fixed point == reference Dijkstra distances bitwise.
#define SWEEP()                                                                \
    do {                                                                       \
        float tl  = O[rt * SROW + tx];                                         \
        float tce = E[rt * SROW + tx];                                         \
        float tco = O[rt * SROW + tx + 1];                                     \
        float tre = E[rt * SROW + tx + 1];                                     \
        float bl  = O[rb * SROW + tx];                                         \
        float bce = E[rb * SROW + tx];                                         \
        float bco = O[rb * SROW + tx + 1];                                     \
        float bre = E[rb * SROW + tx + 1];                                     \
        float l0  = O[ra * SROW + tx];                                         \
        float l1  = O[rc * SROW + tx];                                         \
        float r0  = E[ra * SROW + tx + 1];                                     \
        float r1  = E[rc * SROW + tx + 1];                                     \
        a  = fminf(a,  fminf(fminf(fminf(tl, tce), fminf(tco, l0)),            \
                             fminf(fminf(bv, l1),  fminf(c, d))) + wa);        \
        bv = fminf(bv, fminf(fminf(fminf(tce, tco), fminf(tre, a)),            \
                             fminf(fminf(r0, c),    fminf(d, r1))) + wb);      \
        c  = fminf(c,  fminf(fminf(fminf(l0, a),   fminf(bv, l1)),             \
                             fminf(fminf(d, bl),   fminf(bce, bco))) + wc);    \
        d  = fminf(d,  fminf(fminf(fminf(a, bv),   fminf(r0, c)),              \
                             fminf(fminf(r1, bce), fminf(bco, bre))) + wd);    \
        c  = fminf(c,  fminf(fminf(fminf(l0, a),   fminf(bv, l1)),             \
                             fminf(fminf(d, bl),   fminf(bce, bco))) + wc);    \
        bv = fminf(bv, fminf(fminf(fminf(tce, tco), fminf(tre, a)),            \
                             fminf(fminf(r0, c),    fminf(d, r1))) + wb);      \
        a  = fminf(a,  fminf(fminf(fminf(tl, tce), fminf(tco, l0)),            \
                             fminf(fminf(bv, l1),  fminf(c, d))) + wa);        \
        E[ra * SROW + tx] = a;  O[ra * SROW + tx + 1] = bv;                    \
        E[rc * SROW + tx] = c;  O[rc * SROW + tx + 1] = d;                     \
    } while (0)

    // warm-up: barriers are for termination detection only; >=16 sweeps are
    // always required (16 block-hops source->corner), so run them sync-free.
#pragma unroll 4
    for (int k = 0; k < WARMUP; k++) SWEEP();

    // checked tail: tight ESW=2 epochs, HW barrier-reduction termination
    for (;;) {
        const float sa = a, sb = bv, sc = c, sd = d;
#pragma unroll
        for (int k = 0; k < ESW; k++) SWEEP();
        // registers monotone-decreasing: unchanged epoch everywhere => done
        const int ch = (a != sa) | (bv != sb) | (c != sc) | (d != sd);
        if (!__syncthreads_or(ch)) break;
    }
#undef SWEEP

    // ---- predecessor = argmin over 8 neighbor distances (unique a.s.) ----
    {
        float tl  = Oa[rt * SROW + tx];
        float tce = Ea[rt * SROW + tx];
        float tco = Oa[rt * SROW + tx + 1];
        float tre = Ea[rt * SROW + tx + 1];
        float bl  = Oa[rb * SROW + tx];
        float bce = Ea[rb * SROW + tx];
        float bco = Oa[rb * SROW + tx + 1];
        float bre = Ea[rb * SROW + tx + 1];
        float l0  = Oa[ra * SROW + tx];
        float l1  = Oa[rc * SROW + tx];
        float r0  = Ea[ra * SROW + tx + 1];
        float r1  = Ea[rc * SROW + tx + 1];

        const int A = y0 * GRID_N + x0, B = A + 1, C = A + GRID_N, D = A + GRID_N + 1;

#define ARGMIN8(v1,i1,v2,i2,v3,i3,v4,i4,v5,i5,v6,i6,v7,i7,v8,i8, OUTCELL)      \
        {                                                                       \
            float bd = INF; int bi = 0;                                         \
            if (v1 < bd) { bd = v1; bi = i1; }                                  \
            if (v2 < bd) { bd = v2; bi = i2; }                                  \
            if (v3 < bd) { bd = v3; bi = i3; }                                  \
            if (v4 < bd) { bd = v4; bi = i4; }                                  \
            if (v5 < bd) { bd = v5; bi = i5; }                                  \
            if (v6 < bd) { bd = v6; bi = i6; }                                  \
            if (v7 < bd) { bd = v7; bi = i7; }                                  \
            if (v8 < bd) { bd = v8; bi = i8; }                                  \
            pred[OUTCELL] = (unsigned short)bi;                                 \
        }

        ARGMIN8(tl, A-33, tce, A-32, tco, A-31, l0, A-1, bv, A+1,
                l1, A+31, c, A+32, d, A+33, A)
        ARGMIN8(tce, B-33, tco, B-32, tre, B-31, a, B-1, r0, B+1,
                c, B+31, d, B+32, r1, B+33, B)
        ARGMIN8(l0, C-33, a, C-32, bv, C-31, l1, C-1, d, C+1,
                bl, C+31, bce, C+32, bco, C+33, C)
        ARGMIN8(a, D-33, bv, D-32, r0, D-31, c, D-1, r1, D+1,
                bce, D+31, bco, D+32, bre, D+33, D)
#undef ARGMIN8
    }
    __syncthreads();

    // ---- skip pointers: pred2 = pred∘pred; pred3/pred4 ----
#pragma unroll
    for (int i = 0; i < 4; i++) {
        const int cell = t + i * NT;
        pred2[cell] = pred[pred[cell]];
    }
    __syncthreads();
#pragma unroll
    for (int i = 0; i < 4; i++) {
        const int cell = t + i * NT;
        const int q = pred2[cell];
        pred3[cell] = pred[q];
        pred4[cell] = pred2[q];
    }
    __syncthreads();

    // ---- backtrack from (31,31), 4 chain cells per iteration ----
    // pred chain strictly decreases dist, so it reaches cell 0.
    if (t == 0) {
        int cur = CELLS - 1;
        for (int i = 0; i < CELLS / 4 + 2; i++) {
            const int m1 = pred[cur];
            const int m2 = pred2[cur];
            const int m3 = pred3[cur];
            const int nx = pred4[cur];
            mark[cur] = 1;
            if (cur == 0) break;
            mark[m1] = 1;
            if (m1 == 0) break;
            mark[m2] = 1;
            if (m2 == 0) break;
            mark[m3] = 1;
            if (m3 == 0) break;
            cur = nx;
        }
    }
    __syncthreads();

    // ---- coalesced float2 output ----
    {
        float2* o2 = (float2*)(out + (size_t)b * CELLS);
        const int A = y0 * GRID_N + x0;
        o2[y0 * 16 + tx]       = make_float2(mark[A]      ? 1.0f : 0.0f,
                                             mark[A + 1]  ? 1.0f : 0.0f);
        o2[(y0 + 1) * 16 + tx] = make_float2(mark[A + 32] ? 1.0f : 0.0f,
                                             mark[A + 33] ? 1.0f : 0.0f);
    }
}

extern "C" void kernel_launch(void* const* d_in, const int* in_sizes, int n_in,
                              void* d_out, int out_size)
{
    const float* w = (const float*)d_in[0];
    float* out = (float*)d_out;
    int batches = in_sizes[0] / CELLS;     // 128
    dijkstra_grid_kernel<<<batches, NT>>>(w, out);
}